// round 12
// baseline (speedup 1.0000x reference)
#include <cuda_runtime.h>
#include <math.h>

// LineFinderLoss, S = 4096 (square). Output tuple packed: d_out[0] = loss,
// d_out[1 + i*S + j] = cost[i][j].
//
// cost[i][j] = 0.5*((in[i,0]-tg[j,0])^2 + (in[i,1]-tg[j,1])^2)
// loss = ALPHA*sum((in-tg)^2) - S*sum_n log(in[n,4]) + sum_ij (in[j,3]-tg[i,j])^2 / S^2
//
// SINGLE fused kernel. No mutable replay state: per-block partial sums are
// plain stores (overwritten every replay), last-block detection uses a
// MONOTONIC counter (ticket % gridDim.x) that is never reset. Hang-impossible
// and bitwise-deterministic.

#define MAXS    4096
#define ALPHA   0.01
#define RTILE   4             // rows per group
#define OCC     5             // 5 blocks/SM, 48-reg budget
#define GRID    (148 * OCC)   // 740 blocks = 5920 warps
#define NSLICE  32            // column slices of 128 cols (32 float4 per warp)
#define WPSLICE (GRID * 8 / NSLICE)   // 185 warps per slice

// ---------------- device scratch (no allocations; nothing ever reset) ------
__device__ double g_part_sq[GRID];   // per-block partial: sum (in-tg)^2
__device__ double g_part_t3[GRID];   // per-block partial: sum (ic3-tg)^2
__device__ double g_part_lg[16];     // per-block partial: sum log(in[:,4])
__device__ unsigned int g_count;     // MONOTONIC completion counter

// ---------------- per-row worker -------------------------------------------
__device__ __forceinline__ void do_row(
    const float4 in, const float4 tg, const float a0, const float a1,
    size_t base, int j4, bool isFirst, bool isLast,
    const float4 t0s, const float4 t1s, const float4 c3,
    const float t0L, const float t1L,
    float* __restrict__ out, int S,
    float& accq, float& acct)
{
    float d, e, u, v;
    d = in.x - tg.x; accq = fmaf(d, d, accq);
    e = c3.x - tg.x; acct = fmaf(e, e, acct);
    d = in.y - tg.y; accq = fmaf(d, d, accq);
    e = c3.y - tg.y; acct = fmaf(e, e, acct);
    d = in.z - tg.z; accq = fmaf(d, d, accq);
    e = c3.z - tg.z; acct = fmaf(e, e, acct);
    d = in.w - tg.w; accq = fmaf(d, d, accq);
    e = c3.w - tg.w; acct = fmaf(e, e, acct);

    float4 cv;
    u = a0 - t0s.x; v = a1 - t1s.x; cv.x = 0.5f * fmaf(u, u, v * v);
    u = a0 - t0s.y; v = a1 - t1s.y; cv.y = 0.5f * fmaf(u, u, v * v);
    u = a0 - t0s.z; v = a1 - t1s.z; cv.z = 0.5f * fmaf(u, u, v * v);
    u = a0 - t0s.w; v = a1 - t1s.w; cv.w = 0.5f * fmaf(u, u, v * v);

    if (!isFirst) {
        // out + base + 4*j4 == cost + base + (4*j4 - 1), 16B aligned
        ((float4*)(out + base))[j4] = cv;
    } else {
        float* crow = out + 1 + base;   // cost row start (cols 0..2)
        crow[0] = cv.y; crow[1] = cv.z; crow[2] = cv.w;
    }
    if (isLast) {
        u = a0 - t0L; v = a1 - t1L;
        out[1 + base + (size_t)(S - 1)] = 0.5f * fmaf(u, u, v * v);
    }
}

// ---------------- fused kernel ---------------------------------------------
// Each WARP owns a fixed 128-column slice. At startup it gathers its column
// operands (t0/t1/c3, 12 scattered loads per lane, one round trip) directly
// from the matrices. Groups of 4 rows are STATICALLY interleaved across the
// 185 warps of each slice — no barriers, no atomics in the loop; warps
// free-run (the R8 win). Blocks 0..15 additionally compute the log-sum
// (one row per thread). Per-block partials are plain stores; the block that
// receives the last monotonic ticket reduces them and writes the loss.
__global__ __launch_bounds__(256, OCC)
void fused_kernel(const float* __restrict__ inp,
                  const float* __restrict__ tgt,
                  float* __restrict__ out, int S) {
    const int tid   = threadIdx.x;
    const int lane  = tid & 31;
    const int wid   = tid >> 5;
    const int gw    = blockIdx.x * 8 + wid;          // global warp id
    const int slice = gw & (NSLICE - 1);
    const int wis   = gw >> 5;                       // warp index within slice (0..184)
    const int j4    = slice * 32 + lane;             // float4 column index
    const int lastj4 = (S >> 2) - 1;
    const int groups = S / RTILE;                    // 1024
    const bool isFirst = (j4 == 0);
    const bool isLast  = (j4 == lastj4);

    // ---- log-sum side job: blocks 0..15, one row per thread ----
    float lg = 0.0f;
    if (blockIdx.x < 16) {
        const int rb = blockIdx.x * 256 + tid;
        lg = logf(__ldg(inp + (size_t)rb * S + 4));
    }

    // ---- column gather: 12 scattered loads per lane, once per warp ----
    const int r4 = 4 * j4;
    float4 t0s, t1s, c3;
    t0s.x = (r4 > 0) ? __ldg(tgt + (size_t)(r4 - 1) * S) : 0.0f;
    t0s.y = __ldg(tgt + (size_t)(r4 + 0) * S);
    t0s.z = __ldg(tgt + (size_t)(r4 + 1) * S);
    t0s.w = __ldg(tgt + (size_t)(r4 + 2) * S);
    t1s.x = (r4 > 0) ? __ldg(tgt + (size_t)(r4 - 1) * S + 1) : 0.0f;
    t1s.y = __ldg(tgt + (size_t)(r4 + 0) * S + 1);
    t1s.z = __ldg(tgt + (size_t)(r4 + 1) * S + 1);
    t1s.w = __ldg(tgt + (size_t)(r4 + 2) * S + 1);
    c3.x  = __ldg(inp + (size_t)(r4 + 0) * S + 3);
    c3.y  = __ldg(inp + (size_t)(r4 + 1) * S + 3);
    c3.z  = __ldg(inp + (size_t)(r4 + 2) * S + 3);
    c3.w  = __ldg(inp + (size_t)(r4 + 3) * S + 3);
    const float t0L = isLast ? __ldg(tgt + (size_t)(S - 1) * S)     : 0.0f;
    const float t1L = isLast ? __ldg(tgt + (size_t)(S - 1) * S + 1) : 0.0f;

    // ---- reduce + store log partial (early, so it's done before the fence) --
    __shared__ float wlg[8];
    {
        float l = lg;
        #pragma unroll
        for (int off = 16; off > 0; off >>= 1)
            l += __shfl_down_sync(0xffffffffu, l, off);
        if (lane == 0) wlg[wid] = l;
    }

    float acc_sq0 = 0.0f, acc_sq1 = 0.0f;
    float acc_t30 = 0.0f, acc_t31 = 0.0f;

    // ---- main loop: statically interleaved groups, barrier-free ----
    for (int g = wis; g < groups; g += WPSLICE) {
        const int r0 = g * RTILE;
        const size_t b0 = (size_t)r0 * S;

        // ---- half 1: rows A,B ----
        {
            const float4 iA = __ldcs((const float4*)(inp + b0) + j4);
            const float4 gA = __ldcs((const float4*)(tgt + b0) + j4);
            const float4 iB = __ldcs((const float4*)(inp + b0 + S) + j4);
            const float4 gB = __ldcs((const float4*)(tgt + b0 + S) + j4);
            const float a00 = __ldg(inp + b0),     a01 = __ldg(inp + b0 + 1);
            const float a10 = __ldg(inp + b0 + S), a11 = __ldg(inp + b0 + S + 1);
            do_row(iA, gA, a00, a01, b0,     j4, isFirst, isLast,
                   t0s, t1s, c3, t0L, t1L, out, S, acc_sq0, acc_t30);
            do_row(iB, gB, a10, a11, b0 + S, j4, isFirst, isLast,
                   t0s, t1s, c3, t0L, t1L, out, S, acc_sq1, acc_t31);
        }
        // ---- half 2: rows C,D ----
        {
            const size_t b2 = b0 + 2 * (size_t)S;
            const size_t b3 = b0 + 3 * (size_t)S;
            const float4 iC = __ldcs((const float4*)(inp + b2) + j4);
            const float4 gC = __ldcs((const float4*)(tgt + b2) + j4);
            const float4 iD = __ldcs((const float4*)(inp + b3) + j4);
            const float4 gD = __ldcs((const float4*)(tgt + b3) + j4);
            const float a20 = __ldg(inp + b2), a21 = __ldg(inp + b2 + 1);
            const float a30 = __ldg(inp + b3), a31 = __ldg(inp + b3 + 1);
            do_row(iC, gC, a20, a21, b2, j4, isFirst, isLast,
                   t0s, t1s, c3, t0L, t1L, out, S, acc_sq0, acc_t30);
            do_row(iD, gD, a30, a31, b3, j4, isFirst, isLast,
                   t0s, t1s, c3, t0L, t1L, out, S, acc_sq1, acc_t31);
        }
    }

    float acc_sq = acc_sq0 + acc_sq1;
    float acc_t3 = acc_t30 + acc_t31;

    // ---- block reduce (warps re-converge here) ----
    #pragma unroll
    for (int off = 16; off > 0; off >>= 1) {
        acc_sq += __shfl_down_sync(0xffffffffu, acc_sq, off);
        acc_t3 += __shfl_down_sync(0xffffffffu, acc_t3, off);
    }
    __shared__ float s_sq[8], s_t3[8];
    if (lane == 0) { s_sq[wid] = acc_sq; s_t3[wid] = acc_t3; }
    __syncthreads();

    __shared__ bool amLast;
    if (tid == 0) {
        float r1 = 0.0f, r2 = 0.0f, r3 = 0.0f;
        #pragma unroll
        for (int w = 0; w < 8; w++) { r1 += s_sq[w]; r2 += s_t3[w]; r3 += wlg[w]; }
        g_part_sq[blockIdx.x] = (double)r1;      // plain store, no reset needed
        g_part_t3[blockIdx.x] = (double)r2;
        if (blockIdx.x < 16) g_part_lg[blockIdx.x] = (double)r3;
        __threadfence();
        unsigned int ticket = atomicAdd(&g_count, 1u);   // monotonic, never reset
        amLast = ((ticket % (unsigned int)gridDim.x) == (unsigned int)gridDim.x - 1u);
    }
    __syncthreads();

    // ---- finishing block: parallel-reduce all partials, write loss ----
    if (amLast) {
        double a = 0.0, b = 0.0, c = 0.0;
        for (int i = tid; i < GRID; i += 256) {
            a += *((volatile double*)&g_part_sq[i]);
            b += *((volatile double*)&g_part_t3[i]);
        }
        if (tid < 16) c = *((volatile double*)&g_part_lg[tid]);
        #pragma unroll
        for (int off = 16; off > 0; off >>= 1) {
            a += __shfl_down_sync(0xffffffffu, a, off);
            b += __shfl_down_sync(0xffffffffu, b, off);
            c += __shfl_down_sync(0xffffffffu, c, off);
        }
        __shared__ double da[8], db[8], dc[8];
        if (lane == 0) { da[wid] = a; db[wid] = b; dc[wid] = c; }
        __syncthreads();
        if (tid == 0) {
            double sa = 0.0, sb = 0.0, sc = 0.0;
            #pragma unroll
            for (int w = 0; w < 8; w++) { sa += da[w]; sb += db[w]; sc += dc[w]; }
            double Sd = (double)S;
            out[0] = (float)(ALPHA * sa - Sd * sc + sb / (Sd * Sd));
        }
    }
}

// ---------------- launch ----------------
extern "C" void kernel_launch(void* const* d_in, const int* in_sizes, int n_in,
                              void* d_out, int out_size) {
    const float* inp = (const float*)d_in[0];
    const float* tgt = (const float*)d_in[1];
    float* out = (float*)d_out;

    long long n = in_sizes[0];
    int S = 1;
    while ((long long)(S + 1) * (S + 1) <= n) S++;   // integer sqrt (S = 4096)
    if (S > MAXS) S = MAXS;

    fused_kernel<<<GRID, 256>>>(inp, tgt, out, S);
}